// round 1
// baseline (speedup 1.0000x reference)
#include <cuda_runtime.h>
#include <cuda_bf16.h>
#include <cstdint>

#define T_LEN   4096
#define D_DIM   256
#define ATT     50
#define NPAD    64
#define ROWS    128
#define XS      260    // xs row stride (floats): conflict-free for MMA A loads & phase-3 column reads
#define WS      56     // Ws row stride (floats): conflict-free for MMA B loads
#define NBATCH  64
#define EPS     1e-7f

__device__ float g_denom[NBATCH];

__device__ __forceinline__ float tanh_fast(float v) {
    float r;
    asm("tanh.approx.f32 %0, %1;" : "=f"(r) : "f"(v));
    return r;
}

__device__ __forceinline__ uint32_t f2u(float f) { return __float_as_uint(f); }

__global__ void zero_kernel(float* __restrict__ out) {
    int i = blockIdx.x * blockDim.x + threadIdx.x;
    if (i < NBATCH * D_DIM) out[i] = 0.0f;
    if (i < NBATCH) g_denom[i] = 0.0f;
}

__global__ __launch_bounds__(256, 1)
void att_main_kernel(const float* __restrict__ x,
                     const float* __restrict__ Wg,
                     const float* __restrict__ bg,
                     const float* __restrict__ ug,
                     float* __restrict__ out) {
    extern __shared__ float sm[];
    float* xs = sm;                       // ROWS * XS
    float* Ws = xs + ROWS * XS;           // 256 * WS
    float* us = Ws + D_DIM * WS;          // NPAD
    float* bs = us + NPAD;                // NPAD
    float* es = bs + NPAD;                // ROWS

    const int tid   = threadIdx.x;
    const int b     = blockIdx.y;
    const int chunk = blockIdx.x;

    const float* xg = x + ((size_t)b * T_LEN + (size_t)chunk * ROWS) * D_DIM;

    // ---- Stage W into SMEM, rounded to tf32 (RN) to kill truncation bias ----
    for (int i = tid; i < D_DIM * WS; i += 256) {
        int d = i / WS, a = i % WS;
        float w = (a < ATT) ? Wg[d * ATT + a] : 0.0f;
        uint32_t wi;
        asm("cvt.rna.tf32.f32 %0, %1;" : "=r"(wi) : "f"(w));
        Ws[i] = __uint_as_float(wi);
    }
    if (tid < NPAD) {
        us[tid] = (tid < ATT) ? ug[tid] : 0.0f;
        bs[tid] = (tid < ATT) ? bg[tid] : 0.0f;
    }

    // ---- Stage x chunk (fp32, kept exact for phase 3) ----
    #pragma unroll 8
    for (int i = tid; i < ROWS * (D_DIM / 4); i += 256) {
        int r  = i >> 6;          // D/4 = 64 float4 per row
        int c4 = i & 63;
        float4 v = ((const float4*)xg)[(size_t)r * 64 + c4];
        *(float4*)&xs[r * XS + c4 * 4] = v;
    }
    __syncthreads();

    // ---- Phase 2: tf32 MMA  scores = tanh(x@W + b) . u  ----
    const int lane = tid & 31;
    const int warp = tid >> 5;
    const int g = lane >> 2;       // group id (row within tile)
    const int t = lane & 3;        // thread in group (k index)
    const int wr = warp * 16;      // warp row base

    float c[8][4];
    #pragma unroll
    for (int nt = 0; nt < 8; nt++) {
        c[nt][0] = 0.f; c[nt][1] = 0.f; c[nt][2] = 0.f; c[nt][3] = 0.f;
    }

    const float* xrow0 = xs + (wr + g) * XS;
    const float* xrow1 = xrow0 + 8 * XS;

    #pragma unroll 4
    for (int k0 = 0; k0 < D_DIM; k0 += 8) {
        uint32_t a0 = f2u(xrow0[k0 + t]);
        uint32_t a1 = f2u(xrow1[k0 + t]);
        uint32_t a2 = f2u(xrow0[k0 + t + 4]);
        uint32_t a3 = f2u(xrow1[k0 + t + 4]);
        const float* wk0 = Ws + (k0 + t) * WS;
        const float* wk1 = wk0 + 4 * WS;
        #pragma unroll
        for (int nt = 0; nt < 8; nt++) {
            uint32_t b0 = f2u(wk0[nt * 8 + g]);
            uint32_t b1 = f2u(wk1[nt * 8 + g]);
            asm volatile(
                "mma.sync.aligned.m16n8k8.row.col.f32.tf32.tf32.f32 "
                "{%0,%1,%2,%3}, {%4,%5,%6,%7}, {%8,%9}, {%0,%1,%2,%3};"
                : "+f"(c[nt][0]), "+f"(c[nt][1]), "+f"(c[nt][2]), "+f"(c[nt][3])
                : "r"(a0), "r"(a1), "r"(a2), "r"(a3), "r"(b0), "r"(b1));
        }
    }

    // scores: each lane holds cols {nt*8 + 2t, +1} for rows (wr+g) and (wr+g+8)
    float slo = 0.f, shi = 0.f;
    #pragma unroll
    for (int nt = 0; nt < 8; nt++) {
        int a0c = nt * 8 + 2 * t;
        float u0 = us[a0c], u1 = us[a0c + 1];
        float B0 = bs[a0c], B1 = bs[a0c + 1];
        slo += tanh_fast(c[nt][0] + B0) * u0 + tanh_fast(c[nt][1] + B1) * u1;
        shi += tanh_fast(c[nt][2] + B0) * u0 + tanh_fast(c[nt][3] + B1) * u1;
    }
    // reduce over the 4 lanes of the group (t = 0..3)
    slo += __shfl_xor_sync(0xFFFFFFFFu, slo, 1);
    slo += __shfl_xor_sync(0xFFFFFFFFu, slo, 2);
    shi += __shfl_xor_sync(0xFFFFFFFFu, shi, 1);
    shi += __shfl_xor_sync(0xFFFFFFFFu, shi, 2);
    if (t == 0) {
        es[wr + g]     = __expf(slo) ;
        es[wr + g + 8] = __expf(shi);
    }
    __syncthreads();

    // ---- Phase 3: per-column weighted sum with exact fp32 x ----
    float p0 = 0.f, p1 = 0.f, p2 = 0.f, p3 = 0.f;
    #pragma unroll 8
    for (int r = 0; r < ROWS; r += 4) {
        p0 += es[r + 0] * xs[(r + 0) * XS + tid];
        p1 += es[r + 1] * xs[(r + 1) * XS + tid];
        p2 += es[r + 2] * xs[(r + 2) * XS + tid];
        p3 += es[r + 3] * xs[(r + 3) * XS + tid];
    }
    float acc = (p0 + p1) + (p2 + p3);
    atomicAdd(&out[b * D_DIM + tid], acc);

    // ---- denominator: warp 0 reduces e over 128 rows ----
    if (warp == 0) {
        float s = es[lane] + es[lane + 32] + es[lane + 64] + es[lane + 96];
        #pragma unroll
        for (int o = 16; o > 0; o >>= 1) s += __shfl_xor_sync(0xFFFFFFFFu, s, o);
        if (lane == 0) atomicAdd(&g_denom[b], s);
    }
}

__global__ void norm_kernel(float* __restrict__ out) {
    int i = blockIdx.x * blockDim.x + threadIdx.x;
    if (i < NBATCH * D_DIM) {
        out[i] = out[i] / (g_denom[i >> 8] + EPS);
    }
}

extern "C" void kernel_launch(void* const* d_in, const int* in_sizes, int n_in,
                              void* d_out, int out_size) {
    const float* x = (const float*)d_in[0];
    const float* W = (const float*)d_in[1];
    const float* b = (const float*)d_in[2];
    const float* u = (const float*)d_in[3];
    float* out = (float*)d_out;

    const int smem_bytes = (ROWS * XS + D_DIM * WS + NPAD + NPAD + ROWS) * sizeof(float);
    static bool attr_set = false;
    if (!attr_set) {
        cudaFuncSetAttribute(att_main_kernel,
                             cudaFuncAttributeMaxDynamicSharedMemorySize, smem_bytes);
        attr_set = true;
    }

    zero_kernel<<<(NBATCH * D_DIM + 255) / 256, 256>>>(out);
    att_main_kernel<<<dim3(T_LEN / ROWS, NBATCH), 256, smem_bytes>>>(x, W, b, u, out);
    norm_kernel<<<(NBATCH * D_DIM + 255) / 256, 256>>>(out);
}

// round 2
// speedup vs baseline: 1.6450x; 1.6450x over previous
#include <cuda_runtime.h>
#include <cstdint>

#define T_LEN   4096
#define D_DIM   256
#define ATT     50
#define NPAD    64
#define CH      64      // rows per chunk
#define XS      260     // x row stride (floats): conflict-free MMA A loads & phase-3 column reads
#define WS      56      // W row stride (floats): conflict-free MMA B loads
#define NBATCH  64
#define NCHUNK  (NBATCH * (T_LEN / CH))   // 4096
#define GRID    152
#define EPS     1e-7f

__device__ float g_denom[NBATCH];
__device__ float g_Wp[D_DIM * WS];   // tf32-rounded, zero-padded W
__device__ float g_up[NPAD];
__device__ float g_bp[NPAD];

__device__ __forceinline__ float tanh_fast(float v) {
    float r;
    asm("tanh.approx.f32 %0, %1;" : "=f"(r) : "f"(v));
    return r;
}
__device__ __forceinline__ uint32_t f2u(float f) { return __float_as_uint(f); }

__global__ void prep_kernel(const float* __restrict__ W,
                            const float* __restrict__ b,
                            const float* __restrict__ u,
                            float* __restrict__ out) {
    int i = blockIdx.x * blockDim.x + threadIdx.x;
    if (i < D_DIM * WS) {
        int d = i / WS, a = i % WS;
        float w = (a < ATT) ? W[d * ATT + a] : 0.0f;
        uint32_t wi;
        asm("cvt.rna.tf32.f32 %0, %1;" : "=r"(wi) : "f"(w));
        g_Wp[i] = __uint_as_float(wi);
    }
    if (i < NPAD) {
        g_up[i] = (i < ATT) ? u[i] : 0.0f;
        g_bp[i] = (i < ATT) ? b[i] : 0.0f;
    }
    if (i < NBATCH) g_denom[i] = 0.0f;
    if (i < NBATCH * D_DIM) out[i] = 0.0f;
}

__global__ __launch_bounds__(256, 1)
void att_main_kernel(const float* __restrict__ x, float* __restrict__ out) {
    extern __shared__ float sm[];
    float* xs = sm;                        // 2 * CH * XS
    float* Ws = sm + 2 * CH * XS;          // D_DIM * WS
    float* us = Ws + D_DIM * WS;           // NPAD
    float* bs = us + NPAD;                 // NPAD
    float* es = bs + NPAD;                 // CH
    float* p0 = es + CH;                   // CH
    float* p1 = p0 + CH;                   // CH

    const int tid = threadIdx.x;

    // ---- Stage tf32 W + vectors (once per CTA) ----
    #pragma unroll 4
    for (int i = tid; i < D_DIM * WS / 4; i += 256)
        ((float4*)Ws)[i] = ((const float4*)g_Wp)[i];
    if (tid < NPAD) { us[tid] = g_up[tid]; bs[tid] = g_bp[tid]; }

    const int lane = tid & 31;
    const int warp = tid >> 5;
    const int g = lane >> 2;
    const int t = lane & 3;
    const int mrow = (warp & 3) * 16;
    const int cbase = (warp >> 2) * 32;

    // ---- prefetch helper (inline) ----
    auto prefetch = [&](int c, int bufidx) {
        const float* xg = x + ((size_t)(c >> 6) * T_LEN + (size_t)(c & 63) * CH) * D_DIM;
        float* dst = xs + bufidx * (CH * XS);
        #pragma unroll
        for (int j = 0; j < 16; j++) {
            int i  = j * 256 + tid;        // float4 index within 64x256 tile
            int r  = i >> 6;
            int c4 = i & 63;
            uint32_t sa = (uint32_t)__cvta_generic_to_shared(dst + r * XS + c4 * 4);
            const float4* src = (const float4*)xg + (size_t)r * 64 + c4;
            asm volatile("cp.async.cg.shared.global [%0], [%1], 16;" :: "r"(sa), "l"(src));
        }
        asm volatile("cp.async.commit_group;");
    };

    int c0 = blockIdx.x;
    prefetch(c0, 0);

    int it = 0;
    for (int c = c0; c < NCHUNK; c += GRID, it++) {
        const int nb = it & 1;
        const int cn = c + GRID;
        if (cn < NCHUNK) {
            prefetch(cn, nb ^ 1);
            asm volatile("cp.async.wait_group 1;" ::: "memory");
        } else {
            asm volatile("cp.async.wait_group 0;" ::: "memory");
        }
        __syncthreads();

        const float* cur = xs + nb * (CH * XS);
        const int b = c >> 6;

        // ---- Phase 2: tf32 MMA, warps split over n halves ----
        float cacc[4][4];
        #pragma unroll
        for (int nt = 0; nt < 4; nt++) {
            cacc[nt][0] = 0.f; cacc[nt][1] = 0.f;
            cacc[nt][2] = 0.f; cacc[nt][3] = 0.f;
        }
        const float* xr0 = cur + (mrow + g) * XS;
        const float* xr1 = xr0 + 8 * XS;

        #pragma unroll 4
        for (int k0 = 0; k0 < D_DIM; k0 += 8) {
            uint32_t a0 = f2u(xr0[k0 + t]);
            uint32_t a1 = f2u(xr1[k0 + t]);
            uint32_t a2 = f2u(xr0[k0 + t + 4]);
            uint32_t a3 = f2u(xr1[k0 + t + 4]);
            const float* wk0 = Ws + (k0 + t) * WS + cbase;
            const float* wk1 = wk0 + 4 * WS;
            #pragma unroll
            for (int nt = 0; nt < 4; nt++) {
                uint32_t b0 = f2u(wk0[nt * 8 + g]);
                uint32_t b1 = f2u(wk1[nt * 8 + g]);
                asm volatile(
                    "mma.sync.aligned.m16n8k8.row.col.f32.tf32.tf32.f32 "
                    "{%0,%1,%2,%3}, {%4,%5,%6,%7}, {%8,%9}, {%0,%1,%2,%3};"
                    : "+f"(cacc[nt][0]), "+f"(cacc[nt][1]),
                      "+f"(cacc[nt][2]), "+f"(cacc[nt][3])
                    : "r"(a0), "r"(a1), "r"(a2), "r"(a3), "r"(b0), "r"(b1));
            }
        }

        float slo = 0.f, shi = 0.f;
        #pragma unroll
        for (int nt = 0; nt < 4; nt++) {
            int col = cbase + nt * 8 + 2 * t;
            float u0 = us[col], u1 = us[col + 1];
            float B0 = bs[col], B1 = bs[col + 1];
            slo += tanh_fast(cacc[nt][0] + B0) * u0 + tanh_fast(cacc[nt][1] + B1) * u1;
            shi += tanh_fast(cacc[nt][2] + B0) * u0 + tanh_fast(cacc[nt][3] + B1) * u1;
        }
        slo += __shfl_xor_sync(0xFFFFFFFFu, slo, 1);
        slo += __shfl_xor_sync(0xFFFFFFFFu, slo, 2);
        shi += __shfl_xor_sync(0xFFFFFFFFu, shi, 1);
        shi += __shfl_xor_sync(0xFFFFFFFFu, shi, 2);
        if (t == 0) {
            float* pp = (warp >= 4) ? p1 : p0;
            pp[mrow + g]     = slo;
            pp[mrow + g + 8] = shi;
        }
        __syncthreads();

        // ---- exp + denominator (warp 0) ----
        if (warp == 0) {
            float e0 = __expf(p0[lane]      + p1[lane]);
            float e1 = __expf(p0[lane + 32] + p1[lane + 32]);
            es[lane]      = e0;
            es[lane + 32] = e1;
            float s = e0 + e1;
            #pragma unroll
            for (int o = 16; o > 0; o >>= 1) s += __shfl_xor_sync(0xFFFFFFFFu, s, o);
            if (lane == 0) atomicAdd(&g_denom[b], s);
        }
        __syncthreads();

        // ---- Phase 3: weighted sum over 64 rows, exact fp32 x ----
        float q0 = 0.f, q1 = 0.f, q2 = 0.f, q3 = 0.f;
        #pragma unroll 16
        for (int r = 0; r < CH; r += 4) {
            q0 += es[r + 0] * cur[(r + 0) * XS + tid];
            q1 += es[r + 1] * cur[(r + 1) * XS + tid];
            q2 += es[r + 2] * cur[(r + 2) * XS + tid];
            q3 += es[r + 3] * cur[(r + 3) * XS + tid];
        }
        atomicAdd(&out[b * D_DIM + tid], (q0 + q1) + (q2 + q3));

        __syncthreads();  // protect buffer + es/p reuse before next prefetch
    }
}

__global__ void norm_kernel(float* __restrict__ out) {
    int i = blockIdx.x * blockDim.x + threadIdx.x;
    if (i < NBATCH * D_DIM) {
        out[i] = out[i] / (g_denom[i >> 8] + EPS);
    }
}

extern "C" void kernel_launch(void* const* d_in, const int* in_sizes, int n_in,
                              void* d_out, int out_size) {
    const float* x = (const float*)d_in[0];
    const float* W = (const float*)d_in[1];
    const float* b = (const float*)d_in[2];
    const float* u = (const float*)d_in[3];
    float* out = (float*)d_out;

    const int smem_bytes = (2 * CH * XS + D_DIM * WS + 2 * NPAD + 3 * CH) * sizeof(float);
    cudaFuncSetAttribute(att_main_kernel,
                         cudaFuncAttributeMaxDynamicSharedMemorySize, smem_bytes);

    prep_kernel<<<(D_DIM * WS + 255) / 256, 256>>>(W, b, u, out);
    att_main_kernel<<<GRID, 256, smem_bytes>>>(x, out);
    norm_kernel<<<(NBATCH * D_DIM + 255) / 256, 256>>>(out);
}